// round 3
// baseline (speedup 1.0000x reference)
#include <cuda_runtime.h>
#include <math.h>

// NetVLAD fused kernel, fp32 SIMT + packed FFMA2 (fma.rn.f32x2).
// Shapes: x [64,128,60,80] (P=4800), conv_w [64,128], centroids [64,128],
// out [64, 8192].

#define Nn 64
#define Dd 128
#define Pp 4800
#define Kk 64
#define TP 64          // pixels per tile
#define SPLIT 8        // CTAs per batch along P
#define NTILES (Pp/TP) // 75

#define WS_STRIDE 130  // ws[k][d]
#define XS_STRIDE 68   // xs[d][p]  (even + mult-of-4: LDS.64 pairs + float4)
#define LS_STRIDE 68   // ls[k][p]

#define SMEM_FLOATS (Kk*WS_STRIDE + Dd*XS_STRIDE + Kk*LS_STRIDE)

__device__ float g_agg[Nn * Kk * Dd];
__device__ float g_ssum[Nn * Kk];

// ---- packed f32x2 helpers ------------------------------------------------
typedef unsigned long long u64;

static __device__ __forceinline__ u64 fma2(u64 a, u64 b, u64 c) {
    u64 d;
    asm("fma.rn.f32x2 %0, %1, %2, %3;" : "=l"(d) : "l"(a), "l"(b), "l"(c));
    return d;
}
static __device__ __forceinline__ u64 dup2(float x) {
    u64 d;
    asm("mov.b64 %0, {%1, %1};" : "=l"(d) : "f"(x));
    return d;
}
static __device__ __forceinline__ float hadd2(u64 v) {
    float lo, hi;
    asm("mov.b64 {%0, %1}, %2;" : "=f"(lo), "=f"(hi) : "l"(v));
    return lo + hi;
}

// ---------------------------------------------------------------------------
// Kernel 1: zero scratch
// ---------------------------------------------------------------------------
__global__ void netvlad_zero_kernel() {
    int idx = blockIdx.x * blockDim.x + threadIdx.x;
    int stride = gridDim.x * blockDim.x;
    for (int i = idx; i < Nn * Kk * Dd; i += stride) g_agg[i] = 0.f;
    for (int i = idx; i < Nn * Kk; i += stride)      g_ssum[i] = 0.f;
}

// ---------------------------------------------------------------------------
// Kernel 2: fused normalize + logits GEMM + softmax + aggregation GEMM
// grid = (SPLIT, N), block = 256
// ---------------------------------------------------------------------------
__global__ __launch_bounds__(256, 2)
void netvlad_main_kernel(const float* __restrict__ x,
                         const float* __restrict__ w) {
    extern __shared__ float sh[];
    float* ws = sh;                       // [Kk][WS_STRIDE]
    float* xs = ws + Kk * WS_STRIDE;      // [Dd][XS_STRIDE]
    float* ls = xs + Dd * XS_STRIDE;      // [Kk][LS_STRIDE]

    const int tid = threadIdx.x;
    const int n   = blockIdx.y;
    const int s   = blockIdx.x;

    for (int i = tid; i < Kk * Dd; i += 256) {
        int k = i >> 7, d = i & 127;
        ws[k * WS_STRIDE + d] = w[i];
    }

    const int tk = tid >> 4;      // 0..15
    const int tp = tid & 15;      // 0..15
    const int pix = tid >> 2;     // 0..63
    const int sub = tid & 3;      // 0..3

    // agg accumulators: k = tk+16i, d = tp+16j; packed halves = even/odd p partials
    u64 acc2[4][8];
#pragma unroll
    for (int i = 0; i < 4; i++)
#pragma unroll
        for (int j = 0; j < 8; j++) acc2[i][j] = 0ull;
    float ssum_acc = 0.f;

    const float* xn = x + (size_t)n * Dd * Pp;

    for (int t = s; t < NTILES; t += SPLIT) {
        const int p0 = t * TP;
        __syncthreads();  // xs/ls consumed by previous iteration

        // --- load x tile [Dd][TP]: float4 global -> float4 shared ---
#pragma unroll
        for (int j = 0; j < 8; j++) {
            int idx4 = tid + 256 * j;            // 0..2047
            int d  = idx4 >> 4;
            int p4 = (idx4 & 15) << 2;
            float4 v = *reinterpret_cast<const float4*>(xn + d * Pp + p0 + p4);
            *reinterpret_cast<float4*>(&xs[d * XS_STRIDE + p4]) = v;
        }
        __syncthreads();

        // --- per-pixel L2 normalization over D (4 threads/pixel) ---
        {
            float ssq = 0.f;
#pragma unroll
            for (int i = 0; i < 32; i++) {
                float v = xs[(sub + 4 * i) * XS_STRIDE + pix];
                ssq += v * v;
            }
            ssq += __shfl_xor_sync(0xffffffffu, ssq, 1);
            ssq += __shfl_xor_sync(0xffffffffu, ssq, 2);
            float rin = 1.f / fmaxf(sqrtf(ssq), 1e-12f);
#pragma unroll
            for (int i = 0; i < 32; i++)
                xs[(sub + 4 * i) * XS_STRIDE + pix] *= rin;
        }
        __syncthreads();

        // --- logits GEMM: ls[k][p] = sum_d ws[k][d]*xs[d][p] ---
        // thread: k = tk+16i (i<4), p-pairs at 2*tp + 32*j (j<2), packed over p
        {
            u64 la2[4][2];
#pragma unroll
            for (int i = 0; i < 4; i++) { la2[i][0] = 0ull; la2[i][1] = 0ull; }

#pragma unroll 2
            for (int d = 0; d < Dd; d++) {
                u64 a[4], b[2];
#pragma unroll
                for (int i = 0; i < 4; i++)
                    a[i] = dup2(ws[(tk + 16 * i) * WS_STRIDE + d]);
#pragma unroll
                for (int j = 0; j < 2; j++)
                    b[j] = *reinterpret_cast<const u64*>(
                        &xs[d * XS_STRIDE + 2 * tp + 32 * j]);
#pragma unroll
                for (int i = 0; i < 4; i++)
#pragma unroll
                    for (int j = 0; j < 2; j++)
                        la2[i][j] = fma2(a[i], b[j], la2[i][j]);
            }
#pragma unroll
            for (int i = 0; i < 4; i++)
#pragma unroll
                for (int j = 0; j < 2; j++)
                    *reinterpret_cast<u64*>(
                        &ls[(tk + 16 * i) * LS_STRIDE + 2 * tp + 32 * j]) = la2[i][j];
        }
        __syncthreads();

        // --- softmax over k per pixel (4 threads/pixel) ---
        {
            float m = -1e30f;
#pragma unroll
            for (int i = 0; i < 16; i++)
                m = fmaxf(m, ls[(sub + 4 * i) * LS_STRIDE + pix]);
            m = fmaxf(m, __shfl_xor_sync(0xffffffffu, m, 1));
            m = fmaxf(m, __shfl_xor_sync(0xffffffffu, m, 2));
            float e[16];
            float se = 0.f;
#pragma unroll
            for (int i = 0; i < 16; i++) {
                e[i] = __expf(ls[(sub + 4 * i) * LS_STRIDE + pix] - m);
                se += e[i];
            }
            se += __shfl_xor_sync(0xffffffffu, se, 1);
            se += __shfl_xor_sync(0xffffffffu, se, 2);
            float rs = 1.f / se;
#pragma unroll
            for (int i = 0; i < 16; i++)
                ls[(sub + 4 * i) * LS_STRIDE + pix] = e[i] * rs;
        }
        __syncthreads();

        // --- per-k soft-assign sum over tile ---
        if (tid < Kk) {
            float ssl = 0.f;
#pragma unroll 8
            for (int p = 0; p < TP; p++) ssl += ls[tid * LS_STRIDE + p];
            ssum_acc += ssl;
        }

        // --- aggregation GEMM, packed over p-reduction (pure pair loads) ---
        // acc2[i][j] halves accumulate even/odd p; combined at epilogue.
#pragma unroll 2
        for (int p2 = 0; p2 < TP / 2; p2++) {
            u64 a[4], b[8];
#pragma unroll
            for (int i = 0; i < 4; i++)
                a[i] = *reinterpret_cast<const u64*>(
                    &ls[(tk + 16 * i) * LS_STRIDE + 2 * p2]);
#pragma unroll
            for (int j = 0; j < 8; j++)
                b[j] = *reinterpret_cast<const u64*>(
                    &xs[(tp + 16 * j) * XS_STRIDE + 2 * p2]);
#pragma unroll
            for (int i = 0; i < 4; i++)
#pragma unroll
                for (int j = 0; j < 8; j++)
                    acc2[i][j] = fma2(a[i], b[j], acc2[i][j]);
        }
    }

    // --- merge partials ---
#pragma unroll
    for (int i = 0; i < 4; i++) {
        int k = tk + 16 * i;
#pragma unroll
        for (int j = 0; j < 8; j++) {
            int d = tp + 16 * j;
            atomicAdd(&g_agg[((size_t)n * Kk + k) * Dd + d], hadd2(acc2[i][j]));
        }
    }
    if (tid < Kk) atomicAdd(&g_ssum[n * Kk + tid], ssum_acc);
}

// ---------------------------------------------------------------------------
// Kernel 3: vlad = agg - ssum*centroid, intra L2 norm, global L2 norm
// ---------------------------------------------------------------------------
__global__ __launch_bounds__(256)
void netvlad_finalize_kernel(const float* __restrict__ cent,
                             float* __restrict__ out) {
    __shared__ float sred[256];
    const int n   = blockIdx.x;
    const int tid = threadIdx.x;
    const int k   = tid >> 2;
    const int sub = tid & 3;
    const int dbase = sub * 32;

    float v[32];
    const float ssk = g_ssum[n * Kk + k];
    const float* ap = &g_agg[((size_t)n * Kk + k) * Dd + dbase];
    const float* cp = &cent[k * Dd + dbase];

    float ssq = 0.f;
#pragma unroll
    for (int q = 0; q < 8; q++) {
        float4 a = *reinterpret_cast<const float4*>(ap + 4 * q);
        float4 c = *reinterpret_cast<const float4*>(cp + 4 * q);
        float v0 = a.x - ssk * c.x;
        float v1 = a.y - ssk * c.y;
        float v2 = a.z - ssk * c.z;
        float v3 = a.w - ssk * c.w;
        v[4 * q + 0] = v0; v[4 * q + 1] = v1;
        v[4 * q + 2] = v2; v[4 * q + 3] = v3;
        ssq += v0 * v0 + v1 * v1 + v2 * v2 + v3 * v3;
    }
    ssq += __shfl_xor_sync(0xffffffffu, ssq, 1);
    ssq += __shfl_xor_sync(0xffffffffu, ssq, 2);
    const float rin = 1.f / fmaxf(sqrtf(ssq), 1e-12f);

    sred[tid] = (sub == 0) ? ssq * rin * rin : 0.f;
    __syncthreads();
    for (int st = 128; st > 0; st >>= 1) {
        if (tid < st) sred[tid] += sred[tid + st];
        __syncthreads();
    }
    const float rg = 1.f / fmaxf(sqrtf(sred[0]), 1e-12f);
    const float sc = rin * rg;

    float* op = out + (size_t)n * Kk * Dd + k * Dd + dbase;
#pragma unroll
    for (int q = 0; q < 8; q++) {
        float4 o;
        o.x = v[4 * q + 0] * sc;
        o.y = v[4 * q + 1] * sc;
        o.z = v[4 * q + 2] * sc;
        o.w = v[4 * q + 3] * sc;
        *reinterpret_cast<float4*>(op + 4 * q) = o;
    }
}

// ---------------------------------------------------------------------------
extern "C" void kernel_launch(void* const* d_in, const int* in_sizes, int n_in,
                              void* d_out, int out_size) {
    const float* x    = (const float*)d_in[0];
    const float* w    = (const float*)d_in[1];
    const float* cent = (const float*)d_in[2];
    float* out = (float*)d_out;

    const size_t smem = (size_t)SMEM_FLOATS * sizeof(float);
    cudaFuncSetAttribute(netvlad_main_kernel,
                         cudaFuncAttributeMaxDynamicSharedMemorySize, (int)smem);

    netvlad_zero_kernel<<<1032, 512>>>();
    netvlad_main_kernel<<<dim3(SPLIT, Nn), 256, smem>>>(x, w);
    netvlad_finalize_kernel<<<Nn, 256>>>(cent, out);
}

// round 5
// speedup vs baseline: 1.9559x; 1.9559x over previous
#include <cuda_runtime.h>
#include <cuda_bf16.h>
#include <stdint.h>
#include <math.h>

// NetVLAD via mma.sync bf16 tensor cores (sm_103-safe; no tcgen05).
// x [64,128,4800], conv_w [64,128], centroids [64,128], out [64,8192].

#define Nn 64
#define Dd 128
#define Pp 4800
#define Kk 64
#define PT 128
#define NT 38
#define SPLIT 9

// SMEM element strides
#define SB 136      // bf16 tensors row stride (elements) -> 272B rows, 16B-mult
#define SXF 132     // xf fp32 stride
#define SLT 136     // lt fp32 stride

// byte offsets
#define OFF_XF   0        // fp32 xf[128][132] = 67584; union with lt[64][136] f32 (34816)
#define OFF_W    67584    // bf16 [64][136]  = 17408
#define OFF_PD   84992    // bf16 x[p][d] [128][136] = 34816
#define OFF_DP   119808   // bf16 x[d][p] [128][136] = 34816
#define OFF_SA   154624   // bf16 sa[k][p] [64][136] = 17408
#define OFF_RINV 172032   // 128 f32
#define OFF_SSP  172544   // 256 f32
#define SMEM_TOTAL 173568

__device__ float g_aggp[Nn * SPLIT * Kk * Dd];   // per-(n,s) slabs, layout [d][k]
__device__ float g_ssump[Nn * SPLIT * Kk];

static __device__ __forceinline__ uint32_t smem_u32(const void* p) {
    uint32_t a;
    asm("{ .reg .u64 t; cvta.to.shared.u64 t, %1; cvt.u32.u64 %0, t; }" : "=r"(a) : "l"(p));
    return a;
}
static __device__ __forceinline__ void ldm4(unsigned r[4], uint32_t addr) {
    asm volatile("ldmatrix.sync.aligned.m8n8.x4.shared.b16 {%0,%1,%2,%3}, [%4];"
        : "=r"(r[0]), "=r"(r[1]), "=r"(r[2]), "=r"(r[3]) : "r"(addr));
}
static __device__ __forceinline__ void mma_bf16(float c[4], const unsigned a[4],
                                                unsigned b0, unsigned b1) {
    asm volatile("mma.sync.aligned.m16n8k16.row.col.f32.bf16.bf16.f32 "
        "{%0,%1,%2,%3}, {%4,%5,%6,%7}, {%8,%9}, {%0,%1,%2,%3};"
        : "+f"(c[0]), "+f"(c[1]), "+f"(c[2]), "+f"(c[3])
        : "r"(a[0]), "r"(a[1]), "r"(a[2]), "r"(a[3]), "r"(b0), "r"(b1));
}

// ---------------------------------------------------------------------------
__global__ __launch_bounds__(256, 1)
void netvlad_main_kernel(const float* __restrict__ x, const float* __restrict__ w) {
    extern __shared__ char sm[];
    const uint32_t sb = smem_u32(sm);
    const int tid = threadIdx.x;
    const int wid = tid >> 5;
    const int lid = tid & 31;
    const int n = blockIdx.y;
    const int s = blockIdx.x;

    const unsigned lane15 = lid & 15, laneh = lid >> 4;
    const unsigned lane7  = lid & 7,  lane8h = (lid >> 3) & 1;
    const int g = lid >> 2, tq = lid & 3;

    float* xf   = reinterpret_cast<float*>(sm + OFF_XF);
    float* ltf  = reinterpret_cast<float*>(sm + OFF_XF);   // union with xf
    float* ssp  = reinterpret_cast<float*>(sm + OFF_SSP);
    float* rinv = reinterpret_cast<float*>(sm + OFF_RINV);

    // stage conv_w -> bf16 [k][d], stride SB
    for (int i = tid; i < 2048; i += 256) {
        int k = i >> 5, d4 = (i & 31) << 2;
        float4 v = *reinterpret_cast<const float4*>(w + k * Dd + d4);
        __nv_bfloat162 h0 = __floats2bfloat162_rn(v.x, v.y);
        __nv_bfloat162 h1 = __floats2bfloat162_rn(v.z, v.w);
        uint2 u = make_uint2(*reinterpret_cast<uint32_t*>(&h0),
                             *reinterpret_cast<uint32_t*>(&h1));
        *reinterpret_cast<uint2*>(sm + OFF_W + (uint32_t)(k * SB + d4) * 2) = u;
    }

    // persistent GEMM2 accumulators: warp tile 32d x 32k
    const int mw2 = (wid >> 1) * 32, nw2 = (wid & 1) * 32;
    const int mw1 = (wid & 1) * 32,  nw1 = (wid >> 1) * 32;
    float C2[8][4];
#pragma unroll
    for (int i = 0; i < 8; i++)
#pragma unroll
        for (int j = 0; j < 4; j++) C2[i][j] = 0.f;
    float ssum_part = 0.f;

    const float* xn = x + (size_t)n * Dd * Pp;
    const int pfix = lid + 32 * (wid & 3);   // pixel for ssq/transpose phases
    const int h = wid >> 2;                  // d-half / quad phase

    for (int t = s; t < NT; t += SPLIT) {
        const int p0 = t * PT;

        // --- phase1: gmem -> xf fp32 [d][p] (zero-pad past Pp) ---
#pragma unroll
        for (int i = 0; i < 16; i++) {
            int idx = tid + 256 * i;
            int d = idx >> 5, p4 = (idx & 31) << 2;
            float4 v = make_float4(0.f, 0.f, 0.f, 0.f);
            if (p0 + p4 < Pp)
                v = *reinterpret_cast<const float4*>(xn + (size_t)d * Pp + p0 + p4);
            *reinterpret_cast<float4*>(&xf[d * SXF + p4]) = v;
        }
        __syncthreads();

        // --- phase2: ssq per pixel (fp32) ---
        {
            float sq = 0.f;
#pragma unroll
            for (int i = 0; i < 64; i++) {
                float v = xf[(64 * h + i) * SXF + pfix];
                sq += v * v;
            }
            ssp[h * 128 + pfix] = sq;
        }
        __syncthreads();
        if (tid < 128)
            rinv[tid] = 1.f / fmaxf(sqrtf(ssp[tid] + ssp[128 + tid]), 1e-12f);
        __syncthreads();

        // --- phase3a: xf -> bf16 x[d][p] ---
#pragma unroll
        for (int i = 0; i < 16; i++) {
            int row = wid + 8 * i;
            int p4 = lid << 2;
            float4 v = *reinterpret_cast<const float4*>(&xf[row * SXF + p4]);
            float4 rv = *reinterpret_cast<const float4*>(&rinv[p4]);
            __nv_bfloat162 h0 = __floats2bfloat162_rn(v.x * rv.x, v.y * rv.y);
            __nv_bfloat162 h1 = __floats2bfloat162_rn(v.z * rv.z, v.w * rv.w);
            uint2 u = make_uint2(*reinterpret_cast<uint32_t*>(&h0),
                                 *reinterpret_cast<uint32_t*>(&h1));
            *reinterpret_cast<uint2*>(sm + OFF_DP + (uint32_t)(row * SB + p4) * 2) = u;
        }
        // --- phase3b: xf -> bf16 x[p][d] (transpose) ---
        {
            float rv = rinv[pfix];
#pragma unroll
            for (int i = 0; i < 16; i++) {
                int d4 = 4 * h + 8 * i;
                float a0 = xf[(d4 + 0) * SXF + pfix] * rv;
                float a1 = xf[(d4 + 1) * SXF + pfix] * rv;
                float a2 = xf[(d4 + 2) * SXF + pfix] * rv;
                float a3 = xf[(d4 + 3) * SXF + pfix] * rv;
                __nv_bfloat162 h0 = __floats2bfloat162_rn(a0, a1);
                __nv_bfloat162 h1 = __floats2bfloat162_rn(a2, a3);
                uint2 u = make_uint2(*reinterpret_cast<uint32_t*>(&h0),
                                     *reinterpret_cast<uint32_t*>(&h1));
                *reinterpret_cast<uint2*>(sm + OFF_PD + (uint32_t)(pfix * SB + d4) * 2) = u;
            }
        }
        __syncthreads();

        // --- GEMM1: lt[k][p] = w[k][d] * x[p][d]^T (m=64 k, n=128 p, red=d) ---
        {
            float C1[8][4];
#pragma unroll
            for (int i = 0; i < 8; i++)
#pragma unroll
                for (int j = 0; j < 4; j++) C1[i][j] = 0.f;
#pragma unroll
            for (int d0 = 0; d0 < 128; d0 += 16) {
                unsigned a[2][4], bb[2][4];
                ldm4(a[0], sb + OFF_W + (uint32_t)((mw1 + 0  + lane15) * SB + d0 + 8 * laneh) * 2);
                ldm4(a[1], sb + OFF_W + (uint32_t)((mw1 + 16 + lane15) * SB + d0 + 8 * laneh) * 2);
#pragma unroll
                for (int bp = 0; bp < 2; bp++)
                    ldm4(bb[bp], sb + OFF_PD + (uint32_t)(
                        (nw1 + (2 * bp + (int)laneh) * 8 + (int)lane7) * SB
                        + d0 + 8 * lane8h) * 2);
#pragma unroll
                for (int f = 0; f < 2; f++)
#pragma unroll
                    for (int ff = 0; ff < 4; ff++)
                        mma_bf16(C1[f * 4 + ff], a[f],
                                 bb[ff >> 1][(ff & 1) * 2], bb[ff >> 1][(ff & 1) * 2 + 1]);
            }
#pragma unroll
            for (int f = 0; f < 2; f++)
#pragma unroll
                for (int ff = 0; ff < 4; ff++) {
                    int row = mw1 + f * 16 + g;
                    int col = nw1 + ff * 8 + 2 * tq;
                    *reinterpret_cast<float2*>(&ltf[row * SLT + col]) =
                        make_float2(C1[f * 4 + ff][0], C1[f * 4 + ff][1]);
                    *reinterpret_cast<float2*>(&ltf[(row + 8) * SLT + col]) =
                        make_float2(C1[f * 4 + ff][2], C1[f * 4 + ff][3]);
                }
        }
        __syncthreads();

        // --- softmax over k (2 threads/pixel), write sa[k][p] bf16 ---
        {
            int pix = tid >> 1, sub = tid & 1;
            bool valid = (p0 + pix) < Pp;
            float f[32], m = -1e30f;
#pragma unroll
            for (int i = 0; i < 32; i++) {
                f[i] = ltf[(sub + 2 * i) * SLT + pix];
                m = fmaxf(m, f[i]);
            }
            m = fmaxf(m, __shfl_xor_sync(0xffffffffu, m, 1));
            float sum = 0.f;
#pragma unroll
            for (int i = 0; i < 32; i++) { f[i] = __expf(f[i] - m); sum += f[i]; }
            sum += __shfl_xor_sync(0xffffffffu, sum, 1);
            float rs = valid ? (1.f / sum) : 0.f;
#pragma unroll
            for (int i = 0; i < 32; i++)
                *reinterpret_cast<__nv_bfloat16*>(
                    sm + OFF_SA + (uint32_t)((sub + 2 * i) * SB + pix) * 2) =
                    __float2bfloat16(f[i] * rs);
        }
        __syncthreads();

        // --- ssum partial: thread (k=tid>>2, q=tid&3) sums 32 pixels ---
        {
            int kq = tid >> 2, q = tid & 3;
            float ac = 0.f;
#pragma unroll
            for (int j = 0; j < 16; j++) {
                uint32_t u = *reinterpret_cast<uint32_t*>(
                    sm + OFF_SA + (uint32_t)(kq * SB + 32 * q + 2 * j) * 2);
                float2 fv = __bfloat1622float2(*reinterpret_cast<__nv_bfloat162*>(&u));
                ac += fv.x + fv.y;
            }
            ssum_part += ac;
        }

        // --- GEMM2: agg[d][k] += x[d][p] * sa[k][p]^T (m=128 d, n=64 k, red=p) ---
#pragma unroll
        for (int pc = 0; pc < 128; pc += 16) {
            unsigned a[2][4], bb[2][4];
            ldm4(a[0], sb + OFF_DP + (uint32_t)((mw2 + 0  + lane15) * SB + pc + 8 * laneh) * 2);
            ldm4(a[1], sb + OFF_DP + (uint32_t)((mw2 + 16 + lane15) * SB + pc + 8 * laneh) * 2);
#pragma unroll
            for (int bp = 0; bp < 2; bp++)
                ldm4(bb[bp], sb + OFF_SA + (uint32_t)(
                    (nw2 + (2 * bp + (int)laneh) * 8 + (int)lane7) * SB
                    + pc + 8 * lane8h) * 2);
#pragma unroll
            for (int f = 0; f < 2; f++)
#pragma unroll
                for (int ff = 0; ff < 4; ff++)
                    mma_bf16(C2[f * 4 + ff], a[f],
                             bb[ff >> 1][(ff & 1) * 2], bb[ff >> 1][(ff & 1) * 2 + 1]);
        }
        // no sync needed here: next iter's syncs precede any xs/sa overwrite
    }

    // --- epilogue: write per-CTA slab [d][k] (plain STG, no atomics) ---
    {
        float* slab = g_aggp + ((size_t)(n * SPLIT + s) << 13);
#pragma unroll
        for (int f = 0; f < 2; f++)
#pragma unroll
            for (int ff = 0; ff < 4; ff++) {
                int d = mw2 + f * 16 + g;
                int kb = nw2 + ff * 8 + 2 * tq;
                *reinterpret_cast<float2*>(&slab[d * Kk + kb]) =
                    make_float2(C2[f * 4 + ff][0], C2[f * 4 + ff][1]);
                *reinterpret_cast<float2*>(&slab[(d + 8) * Kk + kb]) =
                    make_float2(C2[f * 4 + ff][2], C2[f * 4 + ff][3]);
            }
    }
    __syncthreads();
    ssp[tid] = ssum_part;
    __syncthreads();
    if (tid < Kk)
        g_ssump[(n * SPLIT + s) * Kk + tid] =
            ssp[4 * tid] + ssp[4 * tid + 1] + ssp[4 * tid + 2] + ssp[4 * tid + 3];
}

// ---------------------------------------------------------------------------
__global__ __launch_bounds__(256)
void netvlad_finalize_kernel(const float* __restrict__ cent, float* __restrict__ out) {
    __shared__ float sred[256];
    const int n = blockIdx.x, tid = threadIdx.x;
    const int k = tid >> 2, sub = tid & 3, dbase = sub * 32;

    float ssk = 0.f;
#pragma unroll
    for (int s = 0; s < SPLIT; s++) ssk += g_ssump[(n * SPLIT + s) * Kk + k];

    float A[32];
#pragma unroll
    for (int i = 0; i < 32; i++) A[i] = 0.f;
    for (int s = 0; s < SPLIT; s++) {
        const float* slab = g_aggp + ((size_t)(n * SPLIT + s) << 13);
#pragma unroll
        for (int i = 0; i < 32; i++) A[i] += slab[(dbase + i) * Kk + k];
    }

    float ssq = 0.f;
#pragma unroll
    for (int q = 0; q < 8; q++) {
        float4 c = *reinterpret_cast<const float4*>(&cent[k * Dd + dbase + 4 * q]);
        A[4*q+0] -= ssk * c.x; A[4*q+1] -= ssk * c.y;
        A[4*q+2] -= ssk * c.z; A[4*q+3] -= ssk * c.w;
        ssq += A[4*q+0]*A[4*q+0] + A[4*q+1]*A[4*q+1]
             + A[4*q+2]*A[4*q+2] + A[4*q+3]*A[4*q+3];
    }
    ssq += __shfl_xor_sync(0xffffffffu, ssq, 1);
    ssq += __shfl_xor_sync(0xffffffffu, ssq, 2);
    const float rin = 1.f / fmaxf(sqrtf(ssq), 1e-12f);

    sred[tid] = (sub == 0) ? ssq * rin * rin : 0.f;
    __syncthreads();
    for (int st = 128; st > 0; st >>= 1) {
        if (tid < st) sred[tid] += sred[tid + st];
        __syncthreads();
    }
    const float rg = 1.f / fmaxf(sqrtf(sred[0]), 1e-12f);
    const float sc = rin * rg;

    float* op = out + (size_t)n * Kk * Dd + k * Dd + dbase;
#pragma unroll
    for (int q = 0; q < 8; q++) {
        float4 o;
        o.x = A[4*q+0]*sc; o.y = A[4*q+1]*sc; o.z = A[4*q+2]*sc; o.w = A[4*q+3]*sc;
        *reinterpret_cast<float4*>(op + 4 * q) = o;
    }
}

// ---------------------------------------------------------------------------
extern "C" void kernel_launch(void* const* d_in, const int* in_sizes, int n_in,
                              void* d_out, int out_size) {
    const float* x    = (const float*)d_in[0];
    const float* w    = (const float*)d_in[1];
    const float* cent = (const float*)d_in[2];
    float* out = (float*)d_out;

    cudaFuncSetAttribute(netvlad_main_kernel,
                         cudaFuncAttributeMaxDynamicSharedMemorySize, SMEM_TOTAL);
    netvlad_main_kernel<<<dim3(SPLIT, Nn), 256, SMEM_TOTAL>>>(x, w);
    netvlad_finalize_kernel<<<Nn, 256>>>(cent, out);
}

// round 6
// speedup vs baseline: 3.3013x; 1.6879x over previous
#include <cuda_runtime.h>
#include <cuda_bf16.h>
#include <stdint.h>
#include <math.h>

// NetVLAD via mma.sync bf16 tensor cores, direct bf16 staging + trans-ldmatrix.
// x [64,128,4800], conv_w [64,128], centroids [64,128], out [64,8192].

#define Nn 64
#define Dd 128
#define Pp 4800
#define Kk 64
#define PT 128
#define NT 38
#define SPLIT 4

#define SB 136      // bf16 row stride (elements); 272B rows (16B multiple)
#define SLT 136     // lt fp32 stride

#define OFF_DP   0        // bf16 x[d][p] [128][136] = 34816
#define OFF_W    34816    // bf16 w[k][d] [64][136]  = 17408
#define OFF_SA   52224    // bf16 sa'[k][p] [64][136] = 17408
#define OFF_LT   69632    // f32 lt[k][p] [64][136]  = 34816
#define OFF_SSP  104448   // 256 f32
#define OFF_RINV 105472   // 128 f32
#define OFF_G    105984   // 128 f32 (norm = 1/rinv)
#define SMEM_TOTAL 106496

__device__ float g_aggp[Nn * SPLIT * Kk * Dd];   // per-(n,s) slabs [d][k]
__device__ float g_ssump[Nn * SPLIT * Kk];

static __device__ __forceinline__ uint32_t smem_u32(const void* p) {
    uint32_t a;
    asm("{ .reg .u64 t; cvta.to.shared.u64 t, %1; cvt.u32.u64 %0, t; }" : "=r"(a) : "l"(p));
    return a;
}
static __device__ __forceinline__ void ldm4(unsigned r[4], uint32_t addr) {
    asm volatile("ldmatrix.sync.aligned.m8n8.x4.shared.b16 {%0,%1,%2,%3}, [%4];"
        : "=r"(r[0]), "=r"(r[1]), "=r"(r[2]), "=r"(r[3]) : "r"(addr));
}
static __device__ __forceinline__ void ldm4t(unsigned r[4], uint32_t addr) {
    asm volatile("ldmatrix.sync.aligned.m8n8.x4.trans.shared.b16 {%0,%1,%2,%3}, [%4];"
        : "=r"(r[0]), "=r"(r[1]), "=r"(r[2]), "=r"(r[3]) : "r"(addr));
}
static __device__ __forceinline__ void mma_bf16(float c[4], const unsigned a[4],
                                                unsigned b0, unsigned b1) {
    asm volatile("mma.sync.aligned.m16n8k16.row.col.f32.bf16.bf16.f32 "
        "{%0,%1,%2,%3}, {%4,%5,%6,%7}, {%8,%9}, {%0,%1,%2,%3};"
        : "+f"(c[0]), "+f"(c[1]), "+f"(c[2]), "+f"(c[3])
        : "r"(a[0]), "r"(a[1]), "r"(a[2]), "r"(a[3]), "r"(b0), "r"(b1));
}

// ---------------------------------------------------------------------------
__global__ __launch_bounds__(256, 2)
void netvlad_main_kernel(const float* __restrict__ x, const float* __restrict__ w) {
    extern __shared__ char sm[];
    const uint32_t sb = smem_u32(sm);
    const int tid = threadIdx.x;
    const int wid = tid >> 5;
    const int lid = tid & 31;
    const int n = blockIdx.y;
    const int s = blockIdx.x;

    const unsigned lane15 = lid & 15, laneh = lid >> 4;
    const unsigned lane7  = lid & 7,  lane8h = (lid >> 3) & 1;
    const int g = lid >> 2, tq = lid & 3;

    float* ltf  = reinterpret_cast<float*>(sm + OFF_LT);
    float* ssp  = reinterpret_cast<float*>(sm + OFF_SSP);
    float* rinv = reinterpret_cast<float*>(sm + OFF_RINV);
    float* gsm  = reinterpret_cast<float*>(sm + OFF_G);

    // stage conv_w -> bf16 [k][d]
    for (int i = tid; i < 2048; i += 256) {
        int k = i >> 5, d4 = (i & 31) << 2;
        float4 v = *reinterpret_cast<const float4*>(w + k * Dd + d4);
        __nv_bfloat162 h0 = __floats2bfloat162_rn(v.x, v.y);
        __nv_bfloat162 h1 = __floats2bfloat162_rn(v.z, v.w);
        uint2 u = make_uint2(*reinterpret_cast<uint32_t*>(&h0),
                             *reinterpret_cast<uint32_t*>(&h1));
        *reinterpret_cast<uint2*>(sm + OFF_W + (uint32_t)(k * SB + d4) * 2) = u;
    }

    const int mw2 = (wid >> 1) * 32, nw2 = (wid & 1) * 32;   // GEMM2: d x k
    const int mw1 = (wid & 1) * 32,  nw1 = (wid >> 1) * 32;  // GEMM1: k x p
    float C2[8][4];
#pragma unroll
    for (int i = 0; i < 8; i++)
#pragma unroll
        for (int j = 0; j < 4; j++) C2[i][j] = 0.f;
    float ssum_part = 0.f;

    const float* xn = x + (size_t)n * Dd * Pp;

    for (int t = s; t < NT; t += SPLIT) {
        const int p0 = t * PT;
        __syncthreads();   // DP/SA/lt consumed by previous iteration

        // --- phase1: gmem fp32 -> bf16 DP [d][p] directly (zero-pad) ---
#pragma unroll
        for (int i = 0; i < 16; i++) {
            int idx = tid + 256 * i;
            int d = idx >> 5, p4 = (idx & 31) << 2;
            float4 v = make_float4(0.f, 0.f, 0.f, 0.f);
            if (p0 + p4 < Pp)
                v = *reinterpret_cast<const float4*>(xn + (size_t)d * Pp + p0 + p4);
            __nv_bfloat162 h0 = __floats2bfloat162_rn(v.x, v.y);
            __nv_bfloat162 h1 = __floats2bfloat162_rn(v.z, v.w);
            uint2 u = make_uint2(*reinterpret_cast<uint32_t*>(&h0),
                                 *reinterpret_cast<uint32_t*>(&h1));
            *reinterpret_cast<uint2*>(sm + OFF_DP + (uint32_t)(d * SB + p4) * 2) = u;
        }
        __syncthreads();

        // --- phase2: ssq per pixel from bf16 tile ---
        if (tid < 128) {
            int h = tid >> 6, tp = tid & 63;   // pixels 2tp, 2tp+1; d-half h
            float s0 = 0.f, s1 = 0.f;
#pragma unroll
            for (int i = 0; i < 64; i++) {
                uint32_t u = *reinterpret_cast<uint32_t*>(
                    sm + OFF_DP + (uint32_t)((64 * h + i) * SB + 2 * tp) * 2);
                float2 f = __bfloat1622float2(*reinterpret_cast<__nv_bfloat162*>(&u));
                s0 += f.x * f.x; s1 += f.y * f.y;
            }
            reinterpret_cast<float2*>(ssp)[h * 64 + tp] = make_float2(s0, s1);
        }
        __syncthreads();
        if (tid < 128) {
            float ss = ssp[tid] + ssp[128 + tid];
            float nrm = fmaxf(sqrtf(ss), 1e-12f);
            rinv[tid] = 1.f / nrm;
            gsm[tid] = nrm;
        }
        __syncthreads();

        // --- GEMM1: lt[k][p] raw = w[k][d] * x[d][p] (B via trans-ldmatrix) ---
        {
            float C1[8][4];
#pragma unroll
            for (int i = 0; i < 8; i++)
#pragma unroll
                for (int j = 0; j < 4; j++) C1[i][j] = 0.f;
#pragma unroll
            for (int d0 = 0; d0 < 128; d0 += 16) {
                unsigned a[2][4], bb[2][4];
                ldm4(a[0], sb + OFF_W + (uint32_t)((mw1 + 0  + lane15) * SB + d0 + 8 * laneh) * 2);
                ldm4(a[1], sb + OFF_W + (uint32_t)((mw1 + 16 + lane15) * SB + d0 + 8 * laneh) * 2);
#pragma unroll
                for (int bp = 0; bp < 2; bp++) {
                    uint32_t row = d0 + 8 * lane8h + lane7;
                    uint32_t col = nw1 + 16 * bp + 8 * laneh;
                    ldm4t(bb[bp], sb + OFF_DP + (row * SB + col) * 2);
                }
#pragma unroll
                for (int f = 0; f < 2; f++)
#pragma unroll
                    for (int ff = 0; ff < 4; ff++)
                        mma_bf16(C1[f * 4 + ff], a[f],
                                 bb[ff >> 1][(ff & 1) * 2], bb[ff >> 1][(ff & 1) * 2 + 1]);
            }
#pragma unroll
            for (int f = 0; f < 2; f++)
#pragma unroll
                for (int ff = 0; ff < 4; ff++) {
                    int row = mw1 + f * 16 + g;
                    int col = nw1 + ff * 8 + 2 * tq;
                    *reinterpret_cast<float2*>(&ltf[row * SLT + col]) =
                        make_float2(C1[f * 4 + ff][0], C1[f * 4 + ff][1]);
                    *reinterpret_cast<float2*>(&ltf[(row + 8) * SLT + col]) =
                        make_float2(C1[f * 4 + ff][2], C1[f * 4 + ff][3]);
                }
        }
        __syncthreads();

        // --- softmax over k (2 thr/pixel); store sa' = softmax * rinv ---
        {
            int pix = tid >> 1, sub = tid & 1;
            bool valid = (p0 + pix) < Pp;
            float rv = rinv[pix];
            float f[32], m = -1e30f;
#pragma unroll
            for (int i = 0; i < 32; i++) {
                f[i] = ltf[(sub + 2 * i) * SLT + pix] * rv;
                m = fmaxf(m, f[i]);
            }
            m = fmaxf(m, __shfl_xor_sync(0xffffffffu, m, 1));
            float sum = 0.f;
#pragma unroll
            for (int i = 0; i < 32; i++) { f[i] = __expf(f[i] - m); sum += f[i]; }
            sum += __shfl_xor_sync(0xffffffffu, sum, 1);
            float rs = valid ? (rv / sum) : 0.f;
#pragma unroll
            for (int i = 0; i < 32; i++)
                *reinterpret_cast<__nv_bfloat16*>(
                    sm + OFF_SA + (uint32_t)((sub + 2 * i) * SB + pix) * 2) =
                    __float2bfloat16(f[i] * rs);
        }
        __syncthreads();

        // --- ssum partial: sum_p sa'[k][p]*norm[p] ---
        {
            int kq = tid >> 2, q = tid & 3;
            float ac = 0.f;
            const float2* gp = reinterpret_cast<const float2*>(gsm);
#pragma unroll
            for (int j = 0; j < 16; j++) {
                uint32_t u = *reinterpret_cast<uint32_t*>(
                    sm + OFF_SA + (uint32_t)(kq * SB + 32 * q + 2 * j) * 2);
                float2 fv = __bfloat1622float2(*reinterpret_cast<__nv_bfloat162*>(&u));
                float2 g2 = gp[16 * q + j];
                ac += fv.x * g2.x + fv.y * g2.y;
            }
            ssum_part += ac;
        }

        // --- GEMM2: agg[d][k] += x[d][p] * sa'[k][p]^T ---
#pragma unroll
        for (int pc = 0; pc < 128; pc += 16) {
            unsigned a[2][4], bb[2][4];
            ldm4(a[0], sb + OFF_DP + (uint32_t)((mw2 + 0  + lane15) * SB + pc + 8 * laneh) * 2);
            ldm4(a[1], sb + OFF_DP + (uint32_t)((mw2 + 16 + lane15) * SB + pc + 8 * laneh) * 2);
#pragma unroll
            for (int bp = 0; bp < 2; bp++)
                ldm4(bb[bp], sb + OFF_SA + (uint32_t)(
                    (nw2 + (2 * bp + (int)laneh) * 8 + (int)lane7) * SB
                    + pc + 8 * lane8h) * 2);
#pragma unroll
            for (int f = 0; f < 2; f++)
#pragma unroll
                for (int ff = 0; ff < 4; ff++)
                    mma_bf16(C2[f * 4 + ff], a[f],
                             bb[ff >> 1][(ff & 1) * 2], bb[ff >> 1][(ff & 1) * 2 + 1]);
        }
    }

    // --- epilogue: per-CTA slab [d][k], plain STG ---
    {
        float* slab = g_aggp + ((size_t)(n * SPLIT + s) << 13);
#pragma unroll
        for (int f = 0; f < 2; f++)
#pragma unroll
            for (int ff = 0; ff < 4; ff++) {
                int d = mw2 + f * 16 + g;
                int kb = nw2 + ff * 8 + 2 * tq;
                *reinterpret_cast<float2*>(&slab[d * Kk + kb]) =
                    make_float2(C2[f * 4 + ff][0], C2[f * 4 + ff][1]);
                *reinterpret_cast<float2*>(&slab[(d + 8) * Kk + kb]) =
                    make_float2(C2[f * 4 + ff][2], C2[f * 4 + ff][3]);
            }
    }
    __syncthreads();
    ssp[tid] = ssum_part;
    __syncthreads();
    if (tid < Kk)
        g_ssump[(n * SPLIT + s) * Kk + tid] =
            ssp[4 * tid] + ssp[4 * tid + 1] + ssp[4 * tid + 2] + ssp[4 * tid + 3];
}

// ---------------------------------------------------------------------------
// Finalize: slab-sum (coalesced) -> smem [128][65] -> per-k + global norms.
// grid = Nn, block = 512.
__global__ __launch_bounds__(512)
void netvlad_finalize_kernel(const float* __restrict__ cent, float* __restrict__ out) {
    __shared__ float stage[128 * 65];
    __shared__ float sred[64];
    __shared__ float stot;
    const int n = blockIdx.x, tid = threadIdx.x;

    // phase A: sum SPLIT slabs, transpose-store into padded stage [d][65]
    const float* base = g_aggp + ((size_t)n * SPLIT << 13);
#pragma unroll
    for (int c = 0; c < 4; c++) {
        int idx = (tid + 512 * c) * 4;
        float4 a = *reinterpret_cast<const float4*>(base + idx);
#pragma unroll
        for (int s2 = 1; s2 < SPLIT; s2++) {
            float4 b = *reinterpret_cast<const float4*>(base + (s2 << 13) + idx);
            a.x += b.x; a.y += b.y; a.z += b.z; a.w += b.w;
        }
        int d = idx >> 6, k = idx & 63;
        stage[d * 65 + k + 0] = a.x;
        stage[d * 65 + k + 1] = a.y;
        stage[d * 65 + k + 2] = a.z;
        stage[d * 65 + k + 3] = a.w;
    }
    __syncthreads();

    // phase B: thread = (k, part); 16 d each
    const int k = tid >> 3, part = tid & 7, dbase = part * 16;
    float ssk = 0.f;
#pragma unroll
    for (int s2 = 0; s2 < SPLIT; s2++)
        ssk += g_ssump[(n * SPLIT + s2) * Kk + k];

    float v[16];
    float ssq = 0.f;
#pragma unroll
    for (int q = 0; q < 4; q++) {
        float4 c = *reinterpret_cast<const float4*>(&cent[k * Dd + dbase + 4 * q]);
        float v0 = stage[(dbase + 4 * q + 0) * 65 + k] - ssk * c.x;
        float v1 = stage[(dbase + 4 * q + 1) * 65 + k] - ssk * c.y;
        float v2 = stage[(dbase + 4 * q + 2) * 65 + k] - ssk * c.z;
        float v3 = stage[(dbase + 4 * q + 3) * 65 + k] - ssk * c.w;
        v[4*q+0] = v0; v[4*q+1] = v1; v[4*q+2] = v2; v[4*q+3] = v3;
        ssq += v0*v0 + v1*v1 + v2*v2 + v3*v3;
    }
    ssq += __shfl_xor_sync(0xffffffffu, ssq, 1);
    ssq += __shfl_xor_sync(0xffffffffu, ssq, 2);
    ssq += __shfl_xor_sync(0xffffffffu, ssq, 4);
    const float rin = 1.f / fmaxf(sqrtf(ssq), 1e-12f);

    if (part == 0) sred[k] = ssq * rin * rin;
    __syncthreads();
    if (tid < 32) {
        float v2 = sred[tid] + sred[tid + 32];
#pragma unroll
        for (int o = 16; o > 0; o >>= 1) v2 += __shfl_xor_sync(0xffffffffu, v2, o);
        if (tid == 0) stot = v2;
    }
    __syncthreads();
    const float rg = 1.f / fmaxf(sqrtf(stot), 1e-12f);
    const float sc = rin * rg;

    float* op = out + (size_t)n * Kk * Dd + k * Dd + dbase;
#pragma unroll
    for (int q = 0; q < 4; q++) {
        float4 o;
        o.x = v[4*q+0]*sc; o.y = v[4*q+1]*sc; o.z = v[4*q+2]*sc; o.w = v[4*q+3]*sc;
        *reinterpret_cast<float4*>(op + 4 * q) = o;
    }
}

// ---------------------------------------------------------------------------
extern "C" void kernel_launch(void* const* d_in, const int* in_sizes, int n_in,
                              void* d_out, int out_size) {
    const float* x    = (const float*)d_in[0];
    const float* w    = (const float*)d_in[1];
    const float* cent = (const float*)d_in[2];
    float* out = (float*)d_out;

    cudaFuncSetAttribute(netvlad_main_kernel,
                         cudaFuncAttributeMaxDynamicSharedMemorySize, SMEM_TOTAL);
    netvlad_main_kernel<<<dim3(SPLIT, Nn), 256, SMEM_TOTAL>>>(x, w);
    netvlad_finalize_kernel<<<Nn, 512>>>(cent, out);
}

// round 7
// speedup vs baseline: 4.3963x; 1.3317x over previous
#include <cuda_runtime.h>
#include <cuda_bf16.h>
#include <stdint.h>
#include <math.h>

// NetVLAD via mma.sync bf16, register-resident softmax.
// x [64,128,4800], conv_w [64,128], centroids [64,128], out [64,8192].

#define Nn 64
#define Dd 128
#define Pp 4800
#define Kk 64
#define PT 128
#define NT 38
#define SPLIT 4

#define SB 136      // bf16 row stride (elements); 272B rows

#define OFF_DP   0        // bf16 x[d][p] [128][136] = 34816
#define OFF_W    34816    // bf16 w[k][d] [64][136]  = 17408
#define OFF_SA   52224    // bf16 sa'[k][p] [64][136] = 17408
#define OFF_SSP  69632    // fp32 [8][128] partial ssq = 4096 (reused as ssw[8][64])
#define OFF_RINV 73728    // 128 f32
#define SMEM_TOTAL 74240

__device__ float g_aggp[Nn * SPLIT * Kk * Dd];   // per-(n,s) slabs [d][k]
__device__ float g_ssump[Nn * SPLIT * Kk];

static __device__ __forceinline__ uint32_t smem_u32(const void* p) {
    uint32_t a;
    asm("{ .reg .u64 t; cvta.to.shared.u64 t, %1; cvt.u32.u64 %0, t; }" : "=r"(a) : "l"(p));
    return a;
}
static __device__ __forceinline__ void ldm4(unsigned r[4], uint32_t addr) {
    asm volatile("ldmatrix.sync.aligned.m8n8.x4.shared.b16 {%0,%1,%2,%3}, [%4];"
        : "=r"(r[0]), "=r"(r[1]), "=r"(r[2]), "=r"(r[3]) : "r"(addr));
}
static __device__ __forceinline__ void ldm4t(unsigned r[4], uint32_t addr) {
    asm volatile("ldmatrix.sync.aligned.m8n8.x4.trans.shared.b16 {%0,%1,%2,%3}, [%4];"
        : "=r"(r[0]), "=r"(r[1]), "=r"(r[2]), "=r"(r[3]) : "r"(addr));
}
static __device__ __forceinline__ void mma_bf16(float c[4], const unsigned a[4],
                                                unsigned b0, unsigned b1) {
    asm volatile("mma.sync.aligned.m16n8k16.row.col.f32.bf16.bf16.f32 "
        "{%0,%1,%2,%3}, {%4,%5,%6,%7}, {%8,%9}, {%0,%1,%2,%3};"
        : "+f"(c[0]), "+f"(c[1]), "+f"(c[2]), "+f"(c[3])
        : "r"(a[0]), "r"(a[1]), "r"(a[2]), "r"(a[3]), "r"(b0), "r"(b1));
}

// ---------------------------------------------------------------------------
__global__ __launch_bounds__(256, 2)
void netvlad_main_kernel(const float* __restrict__ x, const float* __restrict__ w) {
    extern __shared__ char sm[];
    const uint32_t sb = smem_u32(sm);
    const int tid = threadIdx.x;
    const int wid = tid >> 5;
    const int lid = tid & 31;
    const int n = blockIdx.y;
    const int s = blockIdx.x;

    const unsigned lane15 = lid & 15, laneh = lid >> 4;
    const unsigned lane7  = lid & 7,  lane8h = (lid >> 3) & 1;
    const int g = lid >> 2, tq = lid & 3;

    float* ssp  = reinterpret_cast<float*>(sm + OFF_SSP);
    float* rinv = reinterpret_cast<float*>(sm + OFF_RINV);

    // stage conv_w -> bf16 [k][d]
    for (int i = tid; i < 2048; i += 256) {
        int k = i >> 5, d4 = (i & 31) << 2;
        float4 v = *reinterpret_cast<const float4*>(w + k * Dd + d4);
        __nv_bfloat162 h0 = __floats2bfloat162_rn(v.x, v.y);
        __nv_bfloat162 h1 = __floats2bfloat162_rn(v.z, v.w);
        uint2 u = make_uint2(*reinterpret_cast<uint32_t*>(&h0),
                             *reinterpret_cast<uint32_t*>(&h1));
        *reinterpret_cast<uint2*>(sm + OFF_W + (uint32_t)(k * SB + d4) * 2) = u;
    }

    const int pbase = wid * 16;                               // GEMM1 warp p-tile
    const int mw2 = (wid >> 1) * 32, nw2 = (wid & 1) * 32;    // GEMM2: d x k
    float C2[8][4];
#pragma unroll
    for (int i = 0; i < 8; i++)
#pragma unroll
        for (int j = 0; j < 4; j++) C2[i][j] = 0.f;
    float ssum_reg[8];
#pragma unroll
    for (int i = 0; i < 8; i++) ssum_reg[i] = 0.f;

    const float* xn = x + (size_t)n * Dd * Pp;
    const int myp4 = (lid << 2);        // phase1 pixel group (4 pixels)

    for (int t = s; t < NT; t += SPLIT) {
        const int p0 = t * PT;
        __syncthreads();   // DP/SA consumed by previous iteration's GEMM2

        // --- phase1: gmem fp32 -> bf16 DP [d][p]; fused ssq partials ---
        {
            float4 sq = make_float4(0.f, 0.f, 0.f, 0.f);
#pragma unroll
            for (int i = 0; i < 16; i++) {
                int d = wid + 8 * i;
                float4 v = make_float4(0.f, 0.f, 0.f, 0.f);
                if (p0 + myp4 < Pp)
                    v = *reinterpret_cast<const float4*>(xn + (size_t)d * Pp + p0 + myp4);
                sq.x += v.x * v.x; sq.y += v.y * v.y;
                sq.z += v.z * v.z; sq.w += v.w * v.w;
                __nv_bfloat162 h0 = __floats2bfloat162_rn(v.x, v.y);
                __nv_bfloat162 h1 = __floats2bfloat162_rn(v.z, v.w);
                uint2 u = make_uint2(*reinterpret_cast<uint32_t*>(&h0),
                                     *reinterpret_cast<uint32_t*>(&h1));
                *reinterpret_cast<uint2*>(sm + OFF_DP + (uint32_t)(d * SB + myp4) * 2) = u;
            }
            *reinterpret_cast<float4*>(&ssp[wid * 128 + myp4]) = sq;
        }
        __syncthreads();
        if (tid < 128) {
            float ss = 0.f;
#pragma unroll
            for (int wI = 0; wI < 8; wI++) ss += ssp[wI * 128 + tid];
            rinv[tid] = 1.f / fmaxf(sqrtf(ss), 1e-12f);
        }
        __syncthreads();

        // --- GEMM1 (warp: 64k x 16p) + register softmax -> sa' ---
        {
            float C1[8][4];
#pragma unroll
            for (int i = 0; i < 8; i++)
#pragma unroll
                for (int j = 0; j < 4; j++) C1[i][j] = 0.f;
#pragma unroll
            for (int d0 = 0; d0 < 128; d0 += 16) {
                unsigned a[4][4], bb[4];
#pragma unroll
                for (int fk = 0; fk < 4; fk++)
                    ldm4(a[fk], sb + OFF_W +
                        (uint32_t)((16 * fk + lane15) * SB + d0 + 8 * laneh) * 2);
                ldm4t(bb, sb + OFF_DP + (uint32_t)(
                    (d0 + 8 * lane8h + lane7) * SB + pbase + 8 * laneh) * 2);
#pragma unroll
                for (int fk = 0; fk < 4; fk++)
#pragma unroll
                    for (int fp = 0; fp < 2; fp++)
                        mma_bf16(C1[fk * 2 + fp], a[fk], bb[fp * 2], bb[fp * 2 + 1]);
            }

            // scale by rinv[p] (4 p-columns per thread: pc = 2*fp + c)
            float rv[2][2];
            {
                float2 r0 = *reinterpret_cast<const float2*>(&rinv[pbase + 2 * tq]);
                float2 r1 = *reinterpret_cast<const float2*>(&rinv[pbase + 8 + 2 * tq]);
                rv[0][0] = r0.x; rv[0][1] = r0.y; rv[1][0] = r1.x; rv[1][1] = r1.y;
            }
#pragma unroll
            for (int fk = 0; fk < 4; fk++)
#pragma unroll
                for (int fp = 0; fp < 2; fp++)
#pragma unroll
                    for (int h = 0; h < 2; h++)
#pragma unroll
                        for (int c = 0; c < 2; c++)
                            C1[fk * 2 + fp][2 * h + c] *= rv[fp][c];

            // per-column max over k: 8 regs + shfl over g (lane bits 2,3,4)
            float mx[2][2];
#pragma unroll
            for (int fp = 0; fp < 2; fp++)
#pragma unroll
                for (int c = 0; c < 2; c++) {
                    float m = -1e30f;
#pragma unroll
                    for (int fk = 0; fk < 4; fk++)
#pragma unroll
                        for (int h = 0; h < 2; h++)
                            m = fmaxf(m, C1[fk * 2 + fp][2 * h + c]);
                    m = fmaxf(m, __shfl_xor_sync(0xffffffffu, m, 4));
                    m = fmaxf(m, __shfl_xor_sync(0xffffffffu, m, 8));
                    m = fmaxf(m, __shfl_xor_sync(0xffffffffu, m, 16));
                    mx[fp][c] = m;
                }
            // exp + sum
            float sumc[2][2];
#pragma unroll
            for (int fp = 0; fp < 2; fp++)
#pragma unroll
                for (int c = 0; c < 2; c++) {
                    float su = 0.f;
#pragma unroll
                    for (int fk = 0; fk < 4; fk++)
#pragma unroll
                        for (int h = 0; h < 2; h++) {
                            float e = __expf(C1[fk * 2 + fp][2 * h + c] - mx[fp][c]);
                            C1[fk * 2 + fp][2 * h + c] = e;
                            su += e;
                        }
                    su += __shfl_xor_sync(0xffffffffu, su, 4);
                    su += __shfl_xor_sync(0xffffffffu, su, 8);
                    su += __shfl_xor_sync(0xffffffffu, su, 16);
                    sumc[fp][c] = su;
                }
            // inv sums with validity mask
            float isum[2][2];
#pragma unroll
            for (int fp = 0; fp < 2; fp++)
#pragma unroll
                for (int c = 0; c < 2; c++) {
                    int p = pbase + 8 * fp + 2 * tq + c;
                    isum[fp][c] = (p0 + p < Pp) ? (1.f / sumc[fp][c]) : 0.f;
                }
            // ssum accumulate + write sa' = softmax * rinv (paired bf16 stores)
#pragma unroll
            for (int fk = 0; fk < 4; fk++)
#pragma unroll
                for (int h = 0; h < 2; h++) {
                    int k = 16 * fk + 8 * h + g;
#pragma unroll
                    for (int fp = 0; fp < 2; fp++) {
                        float s0 = C1[fk * 2 + fp][2 * h + 0] * isum[fp][0];
                        float s1 = C1[fk * 2 + fp][2 * h + 1] * isum[fp][1];
                        ssum_reg[2 * fk + h] += s0 + s1;
                        __nv_bfloat162 hb =
                            __floats2bfloat162_rn(s0 * rv[fp][0], s1 * rv[fp][1]);
                        *reinterpret_cast<uint32_t*>(sm + OFF_SA +
                            (uint32_t)(k * SB + pbase + 8 * fp + 2 * tq) * 2) =
                            *reinterpret_cast<uint32_t*>(&hb);
                    }
                }
        }
        __syncthreads();

        // --- GEMM2: agg[d][k] += x[d][p] * sa'[k][p]^T ---
#pragma unroll
        for (int pc = 0; pc < 128; pc += 16) {
            unsigned a[2][4], bb[2][4];
            ldm4(a[0], sb + OFF_DP + (uint32_t)((mw2 + 0  + lane15) * SB + pc + 8 * laneh) * 2);
            ldm4(a[1], sb + OFF_DP + (uint32_t)((mw2 + 16 + lane15) * SB + pc + 8 * laneh) * 2);
#pragma unroll
            for (int bp = 0; bp < 2; bp++)
                ldm4(bb[bp], sb + OFF_SA + (uint32_t)(
                    (nw2 + (2 * bp + (int)laneh) * 8 + (int)lane7) * SB
                    + pc + 8 * lane8h) * 2);
#pragma unroll
            for (int f = 0; f < 2; f++)
#pragma unroll
                for (int ff = 0; ff < 4; ff++)
                    mma_bf16(C2[f * 4 + ff], a[f],
                             bb[ff >> 1][(ff & 1) * 2], bb[ff >> 1][(ff & 1) * 2 + 1]);
        }
    }

    // --- epilogue: slab [d][k] (plain STG) ---
    {
        float* slab = g_aggp + ((size_t)(n * SPLIT + s) << 13);
#pragma unroll
        for (int f = 0; f < 2; f++)
#pragma unroll
            for (int ff = 0; ff < 4; ff++) {
                int d = mw2 + f * 16 + g;
                int kb = nw2 + ff * 8 + 2 * tq;
                *reinterpret_cast<float2*>(&slab[d * Kk + kb]) =
                    make_float2(C2[f * 4 + ff][0], C2[f * 4 + ff][1]);
                *reinterpret_cast<float2*>(&slab[(d + 8) * Kk + kb]) =
                    make_float2(C2[f * 4 + ff][2], C2[f * 4 + ff][3]);
            }
    }
    // --- ssum: reduce over tq lanes, then across warps via smem ---
    __syncthreads();
#pragma unroll
    for (int m = 0; m < 8; m++) {
        ssum_reg[m] += __shfl_xor_sync(0xffffffffu, ssum_reg[m], 1);
        ssum_reg[m] += __shfl_xor_sync(0xffffffffu, ssum_reg[m], 2);
    }
    if (tq == 0) {
#pragma unroll
        for (int m = 0; m < 8; m++)
            ssp[wid * 64 + 8 * m + g] = ssum_reg[m];   // reuse ssp as [8][64]
    }
    __syncthreads();
    if (tid < Kk) {
        float ssk = 0.f;
#pragma unroll
        for (int wI = 0; wI < 8; wI++) ssk += ssp[wI * 64 + tid];
        g_ssump[(n * SPLIT + s) * Kk + tid] = ssk;
    }
}

// ---------------------------------------------------------------------------
// Finalize: grid = Nn, block = 1024.
__global__ __launch_bounds__(1024)
void netvlad_finalize_kernel(const float* __restrict__ cent, float* __restrict__ out) {
    __shared__ float stage[128 * 65];
    __shared__ float sred[64];
    __shared__ float stot;
    const int n = blockIdx.x, tid = threadIdx.x;

    const float* base = g_aggp + ((size_t)n * SPLIT << 13);
#pragma unroll
    for (int c = 0; c < 2; c++) {
        int idx = (tid + 1024 * c) * 4;
        float4 a = *reinterpret_cast<const float4*>(base + idx);
#pragma unroll
        for (int s2 = 1; s2 < SPLIT; s2++) {
            float4 b = *reinterpret_cast<const float4*>(base + (s2 << 13) + idx);
            a.x += b.x; a.y += b.y; a.z += b.z; a.w += b.w;
        }
        int d = idx >> 6, k = idx & 63;
        stage[d * 65 + k + 0] = a.x;
        stage[d * 65 + k + 1] = a.y;
        stage[d * 65 + k + 2] = a.z;
        stage[d * 65 + k + 3] = a.w;
    }
    __syncthreads();

    const int k = tid >> 4, part = tid & 15, dbase = part * 8;
    float ssk = 0.f;
#pragma unroll
    for (int s2 = 0; s2 < SPLIT; s2++)
        ssk += g_ssump[(n * SPLIT + s2) * Kk + k];

    float v[8];
    float ssq = 0.f;
#pragma unroll
    for (int q = 0; q < 2; q++) {
        float4 c = *reinterpret_cast<const float4*>(&cent[k * Dd + dbase + 4 * q]);
        float v0 = stage[(dbase + 4 * q + 0) * 65 + k] - ssk * c.x;
        float v1 = stage[(dbase + 4 * q + 1) * 65 + k] - ssk * c.y;
        float v2 = stage[(dbase + 4 * q + 2) * 65 + k] - ssk * c.z;
        float v3 = stage[(dbase + 4 * q + 3) * 65 + k] - ssk * c.w;
        v[4*q+0] = v0; v[4*q+1] = v1; v[4*q+2] = v2; v[4*q+3] = v3;
        ssq += v0*v0 + v1*v1 + v2*v2 + v3*v3;
    }
#pragma unroll
    for (int o = 1; o < 16; o <<= 1)
        ssq += __shfl_xor_sync(0xffffffffu, ssq, o);
    const float rin = 1.f / fmaxf(sqrtf(ssq), 1e-12f);

    if (part == 0) sred[k] = ssq * rin * rin;
    __syncthreads();
    if (tid < 32) {
        float v2 = sred[tid] + sred[tid + 32];
#pragma unroll
        for (int o = 16; o > 0; o >>= 1) v2 += __shfl_xor_sync(0xffffffffu, v2, o);
        if (tid == 0) stot = v2;
    }
    __syncthreads();
    const float rg = 1.f / fmaxf(sqrtf(stot), 1e-12f);
    const float sc = rin * rg;

    float* op = out + (size_t)n * Kk * Dd + k * Dd + dbase;
#pragma unroll
    for (int q = 0; q < 2; q++) {
        float4 o;
        o.x = v[4*q+0]*sc; o.y = v[4*q+1]*sc; o.z = v[4*q+2]*sc; o.w = v[4*q+3]*sc;
        *reinterpret_cast<float4*>(op + 4 * q) = o;
    }
}

// ---------------------------------------------------------------------------
extern "C" void kernel_launch(void* const* d_in, const int* in_sizes, int n_in,
                              void* d_out, int out_size) {
    const float* x    = (const float*)d_in[0];
    const float* w    = (const float*)d_in[1];
    const float* cent = (const float*)d_in[2];
    float* out = (float*)d_out;

    cudaFuncSetAttribute(netvlad_main_kernel,
                         cudaFuncAttributeMaxDynamicSharedMemorySize, SMEM_TOTAL);
    netvlad_main_kernel<<<dim3(SPLIT, Nn), 256, SMEM_TOTAL>>>(x, w);
    netvlad_finalize_kernel<<<Nn, 1024>>>(cent, out);
}